// round 13
// baseline (speedup 1.0000x reference)
#include <cuda_runtime.h>
#include <cuda_fp16.h>
#include <cstdint>

// ============================================================================
// CirculantLinear via length-4 real DFT diagonalization (sm_103-safe ISA:
// cp.async + ldmatrix + mma.sync.m16n8k16.f16; no tcgen05/TMA — harness
// compiles via compute_103 which rejects all "a"-suffix features).
//
//   x (4096x4096 f32), eigens (1024x1024x4 f32) -> out (4096x4096 f32)
//   prep  : x -> Xt = [X0|X2|Xr|Xi] (half); eigens -> W0*, W2* (x0.25),
//           W1* (x0.5, packed [[Er,-Ei],[Ei,Er]])  — inverse-DFT scales are
//           folded into W (exact powers of two, no extra rounding).
//   ONE merged GEMM launch (1024 tiles, 3 logical GEMMs, f32 accum,
//           f16 stores to Yt):
//       Yt[:,0:1024]   = X0 * W0^T
//       Yt[:,1024:2048]= X2 * W2^T
//       Yt[:,2048:4096]= [Xr|Xi] * W1^T
//   post  : pure-add inverse combine -> out (f32)
//
// R12 resubmit of R10 (prior round was an infra failure, kernel untested):
//      Yt in half (epilogue half2 stores, post reads 32MB not 64MB),
//      scales folded into prep_w, prep_x+prep_w merged into one launch,
//      post does 2 y-groups/thread with half2 loads + 32B stores.
// ============================================================================

// ------------------------- device scratch (static) --------------------------
__device__ __half g_Xt[(size_t)4096 * 4096];   // 32 MB
__device__ __half g_W0[1024 * 1024];           // 2 MB   (x 0.25)
__device__ __half g_W2[1024 * 1024];           // 2 MB   (x 0.25)
__device__ __half g_W1[(size_t)2048 * 2048];   // 8 MB   (x 0.5)
__device__ __half g_Yt[(size_t)4096 * 4096];   // 32 MB

// ------------------------- PTX helpers --------------------------------------
__device__ __forceinline__ uint32_t smem_u32(const void* p) {
    uint32_t a;
    asm("{ .reg .u64 t; cvta.to.shared.u64 t, %1; cvt.u32.u64 %0, t; }"
        : "=r"(a) : "l"(p));
    return a;
}

__device__ __forceinline__ void cp_async16(uint32_t dst, const void* src) {
    asm volatile("cp.async.cg.shared.global [%0], [%1], 16;"
                 :: "r"(dst), "l"(src) : "memory");
}
#define CP_COMMIT() asm volatile("cp.async.commit_group;" ::: "memory")
#define CP_WAIT(N)  asm volatile("cp.async.wait_group %0;" :: "n"(N) : "memory")

__device__ __forceinline__ void ldsm_x4(uint32_t r[4], uint32_t addr) {
    asm volatile("ldmatrix.sync.aligned.m8n8.x4.shared.b16 {%0,%1,%2,%3}, [%4];"
                 : "=r"(r[0]), "=r"(r[1]), "=r"(r[2]), "=r"(r[3]) : "r"(addr));
}

__device__ __forceinline__ void mma16816(float c[4], const uint32_t a[4],
                                         const uint32_t b[2]) {
    asm volatile(
        "mma.sync.aligned.m16n8k16.row.col.f32.f16.f16.f32 "
        "{%0,%1,%2,%3}, {%4,%5,%6,%7}, {%8,%9}, {%0,%1,%2,%3};"
        : "+f"(c[0]), "+f"(c[1]), "+f"(c[2]), "+f"(c[3])
        : "r"(a[0]), "r"(a[1]), "r"(a[2]), "r"(a[3]), "r"(b[0]), "r"(b[1]));
}

// ------------------------- merged GEMM kernel --------------------------------
// CTA tile 128x128, BK=64 halfs per stage, 3-stage cp.async pipeline,
// 2 CTAs/SM. 8 warps as 4(M) x 2(N): warp tile 32x64.
// smem rows exactly 128 B; XOR swizzle chunk' = chunk ^ (row & 7) keeps
// ldmatrix conflict-free.
static constexpr int BK = 64, STAGES = 3;
static constexpr int AB_BYTES  = 128 * 128;             // 16384 per operand
static constexpr int STG_BYTES = 2 * AB_BYTES;          // 32768 per stage
static constexpr int SMEM_GEMM = STAGES * STG_BYTES;    // 98304

// Tile table (1024 tiles):
//   t in [0,512):    W1 segment (nk2=32) — scheduled FIRST (long tiles)
//   t in [512,768):  W0 segment (nk2=16)
//   t in [768,1024): W2 segment (nk2=16)
__global__ void __launch_bounds__(256, 2) gemm_f16_merged()
{
    extern __shared__ __align__(128) char smem[];
    const uint32_t sb = smem_u32(smem);
    const int tid  = threadIdx.x;
    const int wid  = tid >> 5;
    const int lane = tid & 31;

    // ---- tile decode ----
    const __half* A;           // Xt column window, [4096 rows, lda=4096]
    const __half* B;           // [N, K] row-major (k contiguous)
    __half*       C;           // Yt column window
    int ldb, nk2, m0, n0;
    {
        int t = blockIdx.x;
        if (t < 512) {                       // bin1: [Xr|Xi] * W1^T
            m0 = (t >> 4) * 128; n0 = (t & 15) * 128;
            A = g_Xt + 2048; B = g_W1; C = g_Yt + 2048; ldb = 2048; nk2 = 32;
        } else if (t < 768) {                // bin0: X0 * W0^T
            int u = t - 512;
            m0 = (u >> 3) * 128; n0 = (u & 7) * 128;
            A = g_Xt; B = g_W0; C = g_Yt; ldb = 1024; nk2 = 16;
        } else {                             // bin2: X2 * W2^T
            int u = t - 768;
            m0 = (u >> 3) * 128; n0 = (u & 7) * 128;
            A = g_Xt + 1024; B = g_W2; C = g_Yt + 1024; ldb = 1024; nk2 = 16;
        }
    }
    const int wm = wid & 3;          // M offset wm*32
    const int wn = wid >> 2;         // N offset wn*64

    const __half* Abase = A + (size_t)m0 * 4096;
    const __half* Bbase = B + (size_t)n0 * ldb;

    // --- stage loader: 1024 x 16B chunks each for A and B, 4 per thread ---
    auto load_stage = [&](int s, int kt2) {
        const uint32_t st = sb + s * STG_BYTES;
        const __half* Ag = Abase + kt2 * BK;
        const __half* Bg = Bbase + kt2 * BK;
        #pragma unroll
        for (int i = 0; i < 4; i++) {
            int seg = i * 256 + tid;          // 0..1023
            int row = seg >> 3, c = seg & 7;  // row 0..127, 16B chunk 0..7
            uint32_t so = row * 128 + ((c ^ (row & 7)) << 4);
            cp_async16(st + so,            Ag + (size_t)row * 4096 + c * 8);
            cp_async16(st + AB_BYTES + so, Bg + (size_t)row * ldb  + c * 8);
        }
    };

    float acc[2][8][4];
    #pragma unroll
    for (int mt = 0; mt < 2; mt++)
        #pragma unroll
        for (int nt = 0; nt < 8; nt++)
            #pragma unroll
            for (int i = 0; i < 4; i++) acc[mt][nt][i] = 0.0f;

    // ldmatrix lane addressing (rows + 16B-chunk index within 128B row)
    const int a_row = wm * 32 + (lane & 15);                      // + mt*16
    const int a_cb  = lane >> 4;                                  // chunk bit
    const int arx   = a_row & 7;                                  // swizzle key
    const int b_row = wn * 64 + (lane & 7) + ((lane >> 1) & 8);   // + np*16
    const int b_cb  = (lane >> 3) & 1;
    const int brx   = b_row & 7;

    // --- prologue: stages 0,1 ---
    load_stage(0, 0); CP_COMMIT();
    load_stage(1, 1); CP_COMMIT();

    // --- mainloop: ONE barrier per iteration (slot math as in R8/R9) ---
    int slot = 0;
    for (int kt = 0; kt < nk2; kt++) {
        CP_WAIT(1);
        __syncthreads();

        int kn = kt + 2;
        if (kn < nk2) {
            int ls = slot + 2; if (ls >= 3) ls -= 3;
            load_stage(ls, kn);
        }
        CP_COMMIT();   // commit (possibly empty) keeps group accounting fixed

        const uint32_t As = sb + slot * STG_BYTES;
        const uint32_t Bs = As + AB_BYTES;

        #pragma unroll
        for (int ks = 0; ks < 4; ks++) {      // 4 x (K=16) subchunks
            uint32_t afr[2][4];
            #pragma unroll
            for (int mt = 0; mt < 2; mt++)
                ldsm_x4(afr[mt],
                        As + (a_row + mt * 16) * 128 +
                        (((2 * ks + a_cb) ^ arx) << 4));
            uint32_t bfr[8][2];
            #pragma unroll
            for (int np = 0; np < 4; np++) {
                uint32_t r[4];
                ldsm_x4(r, Bs + (b_row + np * 16) * 128 +
                           (((2 * ks + b_cb) ^ brx) << 4));
                bfr[np * 2 + 0][0] = r[0]; bfr[np * 2 + 0][1] = r[1];
                bfr[np * 2 + 1][0] = r[2]; bfr[np * 2 + 1][1] = r[3];
            }
            #pragma unroll
            for (int mt = 0; mt < 2; mt++)
                #pragma unroll
                for (int nt = 0; nt < 8; nt++)
                    mma16816(acc[mt][nt], afr[mt], bfr[nt]);
        }

        if (++slot == 3) slot = 0;
    }

    // --- epilogue: half2 stores to Yt (32MB total) ---
    const int g = lane >> 2, t4 = lane & 3;
    #pragma unroll
    for (int mt = 0; mt < 2; mt++) {
        int row = m0 + wm * 32 + mt * 16 + g;
        #pragma unroll
        for (int nt = 0; nt < 8; nt++) {
            int col = n0 + wn * 64 + nt * 8 + 2 * t4;
            __half2 v0 = __floats2half2_rn(acc[mt][nt][0], acc[mt][nt][1]);
            __half2 v1 = __floats2half2_rn(acc[mt][nt][2], acc[mt][nt][3]);
            *reinterpret_cast<__half2*>(C + (size_t)row * 4096 + col)       = v0;
            *reinterpret_cast<__half2*>(C + (size_t)(row + 8) * 4096 + col) = v1;
        }
    }
}

// ------------------------- fused prep kernel ---------------------------------
// Blocks [0, 16384): forward rDFT-4 of x -> Xt (half).
// Blocks [16384, 20480): eigens -> W0*, W2*, W1* with inverse-DFT scales
// folded in (W0,W2 x0.25, W1 x0.5 — exact powers of two, applied pre-round).
__global__ void prep_fused_kernel(const float* __restrict__ x,
                                  const float* __restrict__ eg) {
    int blk = blockIdx.x;
    if (blk < 16384) {
        int t = blk * 256 + threadIdx.x;          // < 4096*1024
        int b = t >> 10, g = t & 1023;
        float4 v = *reinterpret_cast<const float4*>(x + ((size_t)b << 12) + (g << 2));
        float e = v.x + v.z, o = v.y + v.w;
        __half* r = g_Xt + ((size_t)b << 12);
        r[g]        = __float2half_rn(e + o);
        r[1024 + g] = __float2half_rn(e - o);
        r[2048 + g] = __float2half_rn(v.x - v.z);
        r[3072 + g] = __float2half_rn(v.w - v.y);
    } else {
        int t = (blk - 16384) * 256 + threadIdx.x;  // < 1024*1024
        int y = t >> 10, xg = t & 1023;
        float4 v = *reinterpret_cast<const float4*>(eg + ((size_t)t << 2));
        float e = v.x + v.z, o = v.y + v.w;
        __half Er  = __float2half_rn(0.5f * (v.x - v.z));
        __half Ei  = __float2half_rn(0.5f * (v.w - v.y));
        __half nEi = __float2half_rn(0.5f * (v.y - v.w));
        g_W0[t] = __float2half_rn(0.25f * (e + o));
        g_W2[t] = __float2half_rn(0.25f * (e - o));
        size_t r1 = (size_t)y * 2048;
        size_t r2 = (size_t)(1024 + y) * 2048;
        g_W1[r1 + xg]        = Er;
        g_W1[r1 + 1024 + xg] = nEi;
        g_W1[r2 + xg]        = Ei;
        g_W1[r2 + 1024 + xg] = Er;
    }
}

// ------------------------- post kernel ---------------------------------------
// Pure-add inverse combine (scales pre-folded into W):
//   out0 = Y0'+Y2'+Yr'; out1 = Y0'-Y2'-Yi'; out2 = Y0'+Y2'-Yr'; out3 = Y0'-Y2'+Yi'
// 2 y-groups per thread: half2 loads, two contiguous float4 stores (32B).
__global__ void post_kernel(float* __restrict__ out) {
    int t = blockIdx.x * blockDim.x + threadIdx.x;     // < 4096*512
    int b = t >> 9, y2 = (t & 511) << 1;
    const __half* r = g_Yt + ((size_t)b << 12);
    float2 Y0 = __half22float2(*reinterpret_cast<const __half2*>(r + y2));
    float2 Y2 = __half22float2(*reinterpret_cast<const __half2*>(r + 1024 + y2));
    float2 Yr = __half22float2(*reinterpret_cast<const __half2*>(r + 2048 + y2));
    float2 Yi = __half22float2(*reinterpret_cast<const __half2*>(r + 3072 + y2));
    float* dst = out + ((size_t)b << 12) + (y2 << 2);
    float4 o0, o1;
    o0.x = (Y0.x + Y2.x) + Yr.x;
    o0.y = (Y0.x - Y2.x) - Yi.x;
    o0.z = (Y0.x + Y2.x) - Yr.x;
    o0.w = (Y0.x - Y2.x) + Yi.x;
    o1.x = (Y0.y + Y2.y) + Yr.y;
    o1.y = (Y0.y - Y2.y) - Yi.y;
    o1.z = (Y0.y + Y2.y) - Yr.y;
    o1.w = (Y0.y - Y2.y) + Yi.y;
    *reinterpret_cast<float4*>(dst)     = o0;
    *reinterpret_cast<float4*>(dst + 4) = o1;
}

// ------------------------- host side ----------------------------------------
extern "C" void kernel_launch(void* const* d_in, const int* in_sizes, int n_in,
                              void* d_out, int out_size)
{
    const float* x  = (const float*)d_in[0];
    const float* eg = (const float*)d_in[1];
    if (n_in >= 2 && in_sizes[0] < in_sizes[1]) {   // x: 16.8M elems, eigens: 4.2M
        const float* t = x; x = eg; eg = t;
    }

    cudaFuncSetAttribute(gemm_f16_merged,
                         cudaFuncAttributeMaxDynamicSharedMemorySize, SMEM_GEMM);

    prep_fused_kernel<<<20480, 256>>>(x, eg);
    gemm_f16_merged<<<1024, 256, SMEM_GEMM>>>();
    post_kernel<<<(4096 * 512) / 256, 256>>>((float*)d_out);
}

// round 14
// speedup vs baseline: 1.4379x; 1.4379x over previous
#include <cuda_runtime.h>
#include <cuda_fp16.h>
#include <cstdint>

// ============================================================================
// CirculantLinear via length-4 real DFT diagonalization (sm_103-safe ISA:
// cp.async + ldmatrix + mma.sync.m16n8k16.f16; no tcgen05/TMA — harness
// compiles via compute_103 which rejects all "a"-suffix features).
//
//   x (4096x4096 f32), eigens (1024x1024x4 f32) -> out (4096x4096 f32)
//   prep  : x -> Xt = [X0|X2|Xr|Xi] (half); eigens -> W0*, W2* (x0.25),
//           W1* (x0.5, packed [[Er,-Ei],[Ei,Er]]) — scales are exact powers
//           of two folded pre-rounding (identical mantissas to unscaled).
//   ONE merged GEMM launch (1024 tiles, 3 logical GEMMs, f32 accum,
//           f32 stores to Yt):
//       Yt[:,0:1024]   = X0 * W0^T
//       Yt[:,1024:2048]= X2 * W2^T
//       Yt[:,2048:4096]= [Xr|Xi] * W1^T
//   post  : pure-add inverse combine -> out (f32)
//
// R14: REVERT the R13 f16-Yt epilogue (suspected register-spill regression in
//      the GEMM mainloop under the 128-reg cap). GEMM is bit-identical to the
//      measured-good R9 kernel. Kept from R13: fused prep launch, power-of-two
//      scale folding into W, pure-add post.
// ============================================================================

// ------------------------- device scratch (static) --------------------------
__device__ __half g_Xt[(size_t)4096 * 4096];   // 32 MB
__device__ __half g_W0[1024 * 1024];           // 2 MB   (x 0.25)
__device__ __half g_W2[1024 * 1024];           // 2 MB   (x 0.25)
__device__ __half g_W1[(size_t)2048 * 2048];   // 8 MB   (x 0.5)
__device__ float  g_Yt[(size_t)4096 * 4096];   // 64 MB

// ------------------------- PTX helpers --------------------------------------
__device__ __forceinline__ uint32_t smem_u32(const void* p) {
    uint32_t a;
    asm("{ .reg .u64 t; cvta.to.shared.u64 t, %1; cvt.u32.u64 %0, t; }"
        : "=r"(a) : "l"(p));
    return a;
}

__device__ __forceinline__ void cp_async16(uint32_t dst, const void* src) {
    asm volatile("cp.async.cg.shared.global [%0], [%1], 16;"
                 :: "r"(dst), "l"(src) : "memory");
}
#define CP_COMMIT() asm volatile("cp.async.commit_group;" ::: "memory")
#define CP_WAIT(N)  asm volatile("cp.async.wait_group %0;" :: "n"(N) : "memory")

__device__ __forceinline__ void ldsm_x4(uint32_t r[4], uint32_t addr) {
    asm volatile("ldmatrix.sync.aligned.m8n8.x4.shared.b16 {%0,%1,%2,%3}, [%4];"
                 : "=r"(r[0]), "=r"(r[1]), "=r"(r[2]), "=r"(r[3]) : "r"(addr));
}

__device__ __forceinline__ void mma16816(float c[4], const uint32_t a[4],
                                         const uint32_t b[2]) {
    asm volatile(
        "mma.sync.aligned.m16n8k16.row.col.f32.f16.f16.f32 "
        "{%0,%1,%2,%3}, {%4,%5,%6,%7}, {%8,%9}, {%0,%1,%2,%3};"
        : "+f"(c[0]), "+f"(c[1]), "+f"(c[2]), "+f"(c[3])
        : "r"(a[0]), "r"(a[1]), "r"(a[2]), "r"(a[3]), "r"(b[0]), "r"(b[1]));
}

// ------------------------- merged GEMM kernel --------------------------------
// CTA tile 128x128, BK=64 halfs per stage, 3-stage cp.async pipeline,
// 2 CTAs/SM. 8 warps as 4(M) x 2(N): warp tile 32x64.
// smem rows exactly 128 B; XOR swizzle chunk' = chunk ^ (row & 7) keeps
// ldmatrix conflict-free.  (Bit-identical to the R9 kernel that measured
// 173.6 us end-to-end.)
static constexpr int BK = 64, STAGES = 3;
static constexpr int AB_BYTES  = 128 * 128;             // 16384 per operand
static constexpr int STG_BYTES = 2 * AB_BYTES;          // 32768 per stage
static constexpr int SMEM_GEMM = STAGES * STG_BYTES;    // 98304

// Tile table (1024 tiles):
//   t in [0,512):    W1 segment (nk2=32) — scheduled FIRST (long tiles)
//   t in [512,768):  W0 segment (nk2=16)
//   t in [768,1024): W2 segment (nk2=16)
__global__ void __launch_bounds__(256, 2) gemm_f16_merged()
{
    extern __shared__ __align__(128) char smem[];
    const uint32_t sb = smem_u32(smem);
    const int tid  = threadIdx.x;
    const int wid  = tid >> 5;
    const int lane = tid & 31;

    // ---- tile decode ----
    const __half* A;           // Xt column window, [4096 rows, lda=4096]
    const __half* B;           // [N, K] row-major (k contiguous)
    float*        C;           // Yt column window
    int ldb, nk2, m0, n0;
    {
        int t = blockIdx.x;
        if (t < 512) {                       // bin1: [Xr|Xi] * W1^T
            m0 = (t >> 4) * 128; n0 = (t & 15) * 128;
            A = g_Xt + 2048; B = g_W1; C = g_Yt + 2048; ldb = 2048; nk2 = 32;
        } else if (t < 768) {                // bin0: X0 * W0^T
            int u = t - 512;
            m0 = (u >> 3) * 128; n0 = (u & 7) * 128;
            A = g_Xt; B = g_W0; C = g_Yt; ldb = 1024; nk2 = 16;
        } else {                             // bin2: X2 * W2^T
            int u = t - 768;
            m0 = (u >> 3) * 128; n0 = (u & 7) * 128;
            A = g_Xt + 1024; B = g_W2; C = g_Yt + 1024; ldb = 1024; nk2 = 16;
        }
    }
    const int wm = wid & 3;          // M offset wm*32
    const int wn = wid >> 2;         // N offset wn*64

    const __half* Abase = A + (size_t)m0 * 4096;
    const __half* Bbase = B + (size_t)n0 * ldb;

    // --- stage loader: 1024 x 16B chunks each for A and B, 4 per thread ---
    auto load_stage = [&](int s, int kt2) {
        const uint32_t st = sb + s * STG_BYTES;
        const __half* Ag = Abase + kt2 * BK;
        const __half* Bg = Bbase + kt2 * BK;
        #pragma unroll
        for (int i = 0; i < 4; i++) {
            int seg = i * 256 + tid;          // 0..1023
            int row = seg >> 3, c = seg & 7;  // row 0..127, 16B chunk 0..7
            uint32_t so = row * 128 + ((c ^ (row & 7)) << 4);
            cp_async16(st + so,            Ag + (size_t)row * 4096 + c * 8);
            cp_async16(st + AB_BYTES + so, Bg + (size_t)row * ldb  + c * 8);
        }
    };

    float acc[2][8][4];
    #pragma unroll
    for (int mt = 0; mt < 2; mt++)
        #pragma unroll
        for (int nt = 0; nt < 8; nt++)
            #pragma unroll
            for (int i = 0; i < 4; i++) acc[mt][nt][i] = 0.0f;

    // ldmatrix lane addressing (rows + 16B-chunk index within 128B row)
    const int a_row = wm * 32 + (lane & 15);                      // + mt*16
    const int a_cb  = lane >> 4;                                  // chunk bit
    const int arx   = a_row & 7;                                  // swizzle key
    const int b_row = wn * 64 + (lane & 7) + ((lane >> 1) & 8);   // + np*16
    const int b_cb  = (lane >> 3) & 1;
    const int brx   = b_row & 7;

    // --- prologue: stages 0,1 ---
    load_stage(0, 0); CP_COMMIT();
    load_stage(1, 1); CP_COMMIT();

    // --- mainloop: ONE barrier per iteration (slot math as in R8/R9) ---
    int slot = 0;
    for (int kt = 0; kt < nk2; kt++) {
        CP_WAIT(1);
        __syncthreads();

        int kn = kt + 2;
        if (kn < nk2) {
            int ls = slot + 2; if (ls >= 3) ls -= 3;
            load_stage(ls, kn);
        }
        CP_COMMIT();   // commit (possibly empty) keeps group accounting fixed

        const uint32_t As = sb + slot * STG_BYTES;
        const uint32_t Bs = As + AB_BYTES;

        #pragma unroll
        for (int ks = 0; ks < 4; ks++) {      // 4 x (K=16) subchunks
            uint32_t afr[2][4];
            #pragma unroll
            for (int mt = 0; mt < 2; mt++)
                ldsm_x4(afr[mt],
                        As + (a_row + mt * 16) * 128 +
                        (((2 * ks + a_cb) ^ arx) << 4));
            uint32_t bfr[8][2];
            #pragma unroll
            for (int np = 0; np < 4; np++) {
                uint32_t r[4];
                ldsm_x4(r, Bs + (b_row + np * 16) * 128 +
                           (((2 * ks + b_cb) ^ brx) << 4));
                bfr[np * 2 + 0][0] = r[0]; bfr[np * 2 + 0][1] = r[1];
                bfr[np * 2 + 1][0] = r[2]; bfr[np * 2 + 1][1] = r[3];
            }
            #pragma unroll
            for (int mt = 0; mt < 2; mt++)
                #pragma unroll
                for (int nt = 0; nt < 8; nt++)
                    mma16816(acc[mt][nt], afr[mt], bfr[nt]);
        }

        if (++slot == 3) slot = 0;
    }

    // --- epilogue: direct f32 stores to Yt (identical to R9) ---
    const int g = lane >> 2, t4 = lane & 3;
    #pragma unroll
    for (int mt = 0; mt < 2; mt++) {
        int row = m0 + wm * 32 + mt * 16 + g;
        #pragma unroll
        for (int nt = 0; nt < 8; nt++) {
            int col = n0 + wn * 64 + nt * 8 + 2 * t4;
            float2 v0 = make_float2(acc[mt][nt][0], acc[mt][nt][1]);
            float2 v1 = make_float2(acc[mt][nt][2], acc[mt][nt][3]);
            *reinterpret_cast<float2*>(C + (size_t)row * 4096 + col)       = v0;
            *reinterpret_cast<float2*>(C + (size_t)(row + 8) * 4096 + col) = v1;
        }
    }
}

// ------------------------- fused prep kernel ---------------------------------
// Blocks [0, 16384): forward rDFT-4 of x -> Xt (half).
// Blocks [16384, 20480): eigens -> W0*, W2*, W1* with inverse-DFT scales
// folded in (W0,W2 x0.25, W1 x0.5 — exact powers of two, applied pre-round).
__global__ void prep_fused_kernel(const float* __restrict__ x,
                                  const float* __restrict__ eg) {
    int blk = blockIdx.x;
    if (blk < 16384) {
        int t = blk * 256 + threadIdx.x;          // < 4096*1024
        int b = t >> 10, g = t & 1023;
        float4 v = *reinterpret_cast<const float4*>(x + ((size_t)b << 12) + (g << 2));
        float e = v.x + v.z, o = v.y + v.w;
        __half* r = g_Xt + ((size_t)b << 12);
        r[g]        = __float2half_rn(e + o);
        r[1024 + g] = __float2half_rn(e - o);
        r[2048 + g] = __float2half_rn(v.x - v.z);
        r[3072 + g] = __float2half_rn(v.w - v.y);
    } else {
        int t = (blk - 16384) * 256 + threadIdx.x;  // < 1024*1024
        int y = t >> 10, xg = t & 1023;
        float4 v = *reinterpret_cast<const float4*>(eg + ((size_t)t << 2));
        float e = v.x + v.z, o = v.y + v.w;
        __half Er  = __float2half_rn(0.5f * (v.x - v.z));
        __half Ei  = __float2half_rn(0.5f * (v.w - v.y));
        __half nEi = __float2half_rn(0.5f * (v.y - v.w));
        g_W0[t] = __float2half_rn(0.25f * (e + o));
        g_W2[t] = __float2half_rn(0.25f * (e - o));
        size_t r1 = (size_t)y * 2048;
        size_t r2 = (size_t)(1024 + y) * 2048;
        g_W1[r1 + xg]        = Er;
        g_W1[r1 + 1024 + xg] = nEi;
        g_W1[r2 + xg]        = Ei;
        g_W1[r2 + 1024 + xg] = Er;
    }
}

// ------------------------- post kernel ---------------------------------------
// Pure-add inverse combine (scales pre-folded into W):
//   out0 = Y0'+Y2'+Yr'; out1 = Y0'-Y2'-Yi'; out2 = Y0'+Y2'-Yr'; out3 = Y0'-Y2'+Yi'
__global__ void post_kernel(float* __restrict__ out) {
    int t = blockIdx.x * blockDim.x + threadIdx.x;     // < 4096*1024
    int b = t >> 10, y = t & 1023;
    const float* r = g_Yt + ((size_t)b << 12);
    float Y0 = r[y], Y2 = r[1024 + y], Yr = r[2048 + y], Yi = r[3072 + y];
    float4 o;
    o.x = (Y0 + Y2) + Yr;
    o.y = (Y0 - Y2) - Yi;
    o.z = (Y0 + Y2) - Yr;
    o.w = (Y0 - Y2) + Yi;
    *reinterpret_cast<float4*>(out + ((size_t)b << 12) + (y << 2)) = o;
}

// ------------------------- host side ----------------------------------------
extern "C" void kernel_launch(void* const* d_in, const int* in_sizes, int n_in,
                              void* d_out, int out_size)
{
    const float* x  = (const float*)d_in[0];
    const float* eg = (const float*)d_in[1];
    if (n_in >= 2 && in_sizes[0] < in_sizes[1]) {   // x: 16.8M elems, eigens: 4.2M
        const float* t = x; x = eg; eg = t;
    }

    cudaFuncSetAttribute(gemm_f16_merged,
                         cudaFuncAttributeMaxDynamicSharedMemorySize, SMEM_GEMM);

    prep_fused_kernel<<<20480, 256>>>(x, eg);
    gemm_f16_merged<<<1024, 256, SMEM_GEMM>>>();
    post_kernel<<<(4096 * 1024) / 256, 256>>>((float*)d_out);
}

// round 15
// speedup vs baseline: 1.4905x; 1.0365x over previous
#include <cuda_runtime.h>
#include <cuda_fp16.h>
#include <cstdint>

// ============================================================================
// CirculantLinear via length-4 real DFT diagonalization (sm_103-safe ISA:
// cp.async + ldmatrix + mma.sync.m16n8k16.f16; no tcgen05/TMA — harness
// compiles via compute_103 which rejects all "a"-suffix features).
//
//   x (4096x4096 f32), eigens (1024x1024x4 f32) -> out (4096x4096 f32)
//   prep  : x -> Xt = [X0|X2|Xr|Xi] (half); eigens -> W0*, W2* (x0.25),
//           W1* (x0.5, packed [[Er,-Ei],[Ei,Er]]) — scales are exact powers
//           of two folded pre-rounding (identical mantissas to unscaled).
//   ONE merged GEMM launch (1024 tiles, 3 logical GEMMs, f32 accum,
//           f16 Yt via SMEM-STAGED epilogue):
//       Yt[:,0:1024]   = X0 * W0^T
//       Yt[:,1024:2048]= X2 * W2^T
//       Yt[:,2048:4096]= [Xr|Xi] * W1^T
//   post  : pure-add inverse combine (half2 loads) -> out (f32)
//
// R15: re-land f16 Yt with an smem-staged epilogue. R13 (direct cvt+half2
//      stores from the acc loop) regressed the MAINLOOP (reg pressure); this
//      version stages through smem (free post-mainloop), so the mainloop is
//      bit-identical to the measured-good R9/R14 kernel, and the final global
//      stores are fully-coalesced 16B chunks of contiguous 256B rows.
// ============================================================================

// ------------------------- device scratch (static) --------------------------
__device__ __half g_Xt[(size_t)4096 * 4096];   // 32 MB
__device__ __half g_W0[1024 * 1024];           // 2 MB   (x 0.25)
__device__ __half g_W2[1024 * 1024];           // 2 MB   (x 0.25)
__device__ __half g_W1[(size_t)2048 * 2048];   // 8 MB   (x 0.5)
__device__ __half g_Yt[(size_t)4096 * 4096];   // 32 MB

// ------------------------- PTX helpers --------------------------------------
__device__ __forceinline__ uint32_t smem_u32(const void* p) {
    uint32_t a;
    asm("{ .reg .u64 t; cvta.to.shared.u64 t, %1; cvt.u32.u64 %0, t; }"
        : "=r"(a) : "l"(p));
    return a;
}

__device__ __forceinline__ void cp_async16(uint32_t dst, const void* src) {
    asm volatile("cp.async.cg.shared.global [%0], [%1], 16;"
                 :: "r"(dst), "l"(src) : "memory");
}
#define CP_COMMIT() asm volatile("cp.async.commit_group;" ::: "memory")
#define CP_WAIT(N)  asm volatile("cp.async.wait_group %0;" :: "n"(N) : "memory")

__device__ __forceinline__ void ldsm_x4(uint32_t r[4], uint32_t addr) {
    asm volatile("ldmatrix.sync.aligned.m8n8.x4.shared.b16 {%0,%1,%2,%3}, [%4];"
                 : "=r"(r[0]), "=r"(r[1]), "=r"(r[2]), "=r"(r[3]) : "r"(addr));
}

__device__ __forceinline__ void mma16816(float c[4], const uint32_t a[4],
                                         const uint32_t b[2]) {
    asm volatile(
        "mma.sync.aligned.m16n8k16.row.col.f32.f16.f16.f32 "
        "{%0,%1,%2,%3}, {%4,%5,%6,%7}, {%8,%9}, {%0,%1,%2,%3};"
        : "+f"(c[0]), "+f"(c[1]), "+f"(c[2]), "+f"(c[3])
        : "r"(a[0]), "r"(a[1]), "r"(a[2]), "r"(a[3]), "r"(b[0]), "r"(b[1]));
}

// ------------------------- merged GEMM kernel --------------------------------
// CTA tile 128x128, BK=64 halfs per stage, 3-stage cp.async pipeline,
// 2 CTAs/SM. 8 warps as 4(M) x 2(N): warp tile 32x64.
// smem rows exactly 128 B; XOR swizzle chunk' = chunk ^ (row & 7) keeps
// ldmatrix conflict-free.  Mainloop bit-identical to R9/R14.
static constexpr int BK = 64, STAGES = 3;
static constexpr int AB_BYTES  = 128 * 128;             // 16384 per operand
static constexpr int STG_BYTES = 2 * AB_BYTES;          // 32768 per stage
static constexpr int SMEM_GEMM = STAGES * STG_BYTES;    // 98304

// Epilogue staging: 128 rows x 272B (256B payload of 128 halfs + 16B pad).
// Bank math: STS half2 at addr row*272 + col*2 -> bank = (68*row + col/2)%32;
// within a warp phase g spans 0..7 (4g: 0,4,..,28) and t4 spans 0..3 -> all
// 32 banks distinct. LDS.128 copy-out: each quarter-warp phase covers 32
// distinct banks. Conflict-free both directions.
static constexpr int EPI_ROW_B = 272;

// Tile table (1024 tiles):
//   t in [0,512):    W1 segment (nk2=32) — scheduled FIRST (long tiles)
//   t in [512,768):  W0 segment (nk2=16)
//   t in [768,1024): W2 segment (nk2=16)
__global__ void __launch_bounds__(256, 2) gemm_f16_merged()
{
    extern __shared__ __align__(128) char smem[];
    const uint32_t sb = smem_u32(smem);
    const int tid  = threadIdx.x;
    const int wid  = tid >> 5;
    const int lane = tid & 31;

    // ---- tile decode ----
    const __half* A;           // Xt column window, [4096 rows, lda=4096]
    const __half* B;           // [N, K] row-major (k contiguous)
    __half*       C;           // Yt column window (half)
    int ldb, nk2, m0, n0;
    {
        int t = blockIdx.x;
        if (t < 512) {                       // bin1: [Xr|Xi] * W1^T
            m0 = (t >> 4) * 128; n0 = (t & 15) * 128;
            A = g_Xt + 2048; B = g_W1; C = g_Yt + 2048; ldb = 2048; nk2 = 32;
        } else if (t < 768) {                // bin0: X0 * W0^T
            int u = t - 512;
            m0 = (u >> 3) * 128; n0 = (u & 7) * 128;
            A = g_Xt; B = g_W0; C = g_Yt; ldb = 1024; nk2 = 16;
        } else {                             // bin2: X2 * W2^T
            int u = t - 768;
            m0 = (u >> 3) * 128; n0 = (u & 7) * 128;
            A = g_Xt + 1024; B = g_W2; C = g_Yt + 1024; ldb = 1024; nk2 = 16;
        }
    }
    const int wm = wid & 3;          // M offset wm*32
    const int wn = wid >> 2;         // N offset wn*64

    const __half* Abase = A + (size_t)m0 * 4096;
    const __half* Bbase = B + (size_t)n0 * ldb;

    // --- stage loader: 1024 x 16B chunks each for A and B, 4 per thread ---
    auto load_stage = [&](int s, int kt2) {
        const uint32_t st = sb + s * STG_BYTES;
        const __half* Ag = Abase + kt2 * BK;
        const __half* Bg = Bbase + kt2 * BK;
        #pragma unroll
        for (int i = 0; i < 4; i++) {
            int seg = i * 256 + tid;          // 0..1023
            int row = seg >> 3, c = seg & 7;  // row 0..127, 16B chunk 0..7
            uint32_t so = row * 128 + ((c ^ (row & 7)) << 4);
            cp_async16(st + so,            Ag + (size_t)row * 4096 + c * 8);
            cp_async16(st + AB_BYTES + so, Bg + (size_t)row * ldb  + c * 8);
        }
    };

    float acc[2][8][4];
    #pragma unroll
    for (int mt = 0; mt < 2; mt++)
        #pragma unroll
        for (int nt = 0; nt < 8; nt++)
            #pragma unroll
            for (int i = 0; i < 4; i++) acc[mt][nt][i] = 0.0f;

    // ldmatrix lane addressing (rows + 16B-chunk index within 128B row)
    const int a_row = wm * 32 + (lane & 15);                      // + mt*16
    const int a_cb  = lane >> 4;                                  // chunk bit
    const int arx   = a_row & 7;                                  // swizzle key
    const int b_row = wn * 64 + (lane & 7) + ((lane >> 1) & 8);   // + np*16
    const int b_cb  = (lane >> 3) & 1;
    const int brx   = b_row & 7;

    // --- prologue: stages 0,1 ---
    load_stage(0, 0); CP_COMMIT();
    load_stage(1, 1); CP_COMMIT();

    // --- mainloop: ONE barrier per iteration (slot math as in R8/R9) ---
    int slot = 0;
    for (int kt = 0; kt < nk2; kt++) {
        CP_WAIT(1);
        __syncthreads();

        int kn = kt + 2;
        if (kn < nk2) {
            int ls = slot + 2; if (ls >= 3) ls -= 3;
            load_stage(ls, kn);
        }
        CP_COMMIT();   // commit (possibly empty) keeps group accounting fixed

        const uint32_t As = sb + slot * STG_BYTES;
        const uint32_t Bs = As + AB_BYTES;

        #pragma unroll
        for (int ks = 0; ks < 4; ks++) {      // 4 x (K=16) subchunks
            uint32_t afr[2][4];
            #pragma unroll
            for (int mt = 0; mt < 2; mt++)
                ldsm_x4(afr[mt],
                        As + (a_row + mt * 16) * 128 +
                        (((2 * ks + a_cb) ^ arx) << 4));
            uint32_t bfr[8][2];
            #pragma unroll
            for (int np = 0; np < 4; np++) {
                uint32_t r[4];
                ldsm_x4(r, Bs + (b_row + np * 16) * 128 +
                           (((2 * ks + b_cb) ^ brx) << 4));
                bfr[np * 2 + 0][0] = r[0]; bfr[np * 2 + 0][1] = r[1];
                bfr[np * 2 + 1][0] = r[2]; bfr[np * 2 + 1][1] = r[3];
            }
            #pragma unroll
            for (int mt = 0; mt < 2; mt++)
                #pragma unroll
                for (int nt = 0; nt < 8; nt++)
                    mma16816(acc[mt][nt], afr[mt], bfr[nt]);
        }

        if (++slot == 3) slot = 0;
    }

    // --- epilogue: smem-staged f16 stores to Yt ---
    CP_WAIT(0);           // drain any (empty) in-flight groups
    __syncthreads();      // all warps finished reading stage smem

    // 1) convert acc -> half2 into staging tile [128][272B]
    {
        const int g = lane >> 2, t4 = lane & 3;
        #pragma unroll
        for (int mt = 0; mt < 2; mt++) {
            int row0 = wm * 32 + mt * 16 + g;
            #pragma unroll
            for (int nt = 0; nt < 8; nt++) {
                int colb = (wn * 64 + nt * 8 + 2 * t4) * 2;   // byte offset
                __half2 h0 = __floats2half2_rn(acc[mt][nt][0], acc[mt][nt][1]);
                __half2 h1 = __floats2half2_rn(acc[mt][nt][2], acc[mt][nt][3]);
                *reinterpret_cast<__half2*>(smem + row0 * EPI_ROW_B + colb)       = h0;
                *reinterpret_cast<__half2*>(smem + (row0 + 8) * EPI_ROW_B + colb) = h1;
            }
        }
    }
    __syncthreads();

    // 2) coalesced copy-out: 128 rows x 16 chunks of 16B, 8 chunks/thread
    #pragma unroll
    for (int i = 0; i < 8; i++) {
        int idx = i * 256 + tid;              // 0..2047
        int row = idx >> 4, c = idx & 15;
        uint4 v = *reinterpret_cast<const uint4*>(smem + row * EPI_ROW_B + c * 16);
        *reinterpret_cast<uint4*>(C + (size_t)(m0 + row) * 4096 + n0 + c * 8) = v;
    }
}

// ------------------------- fused prep kernel ---------------------------------
// Blocks [0, 16384): forward rDFT-4 of x -> Xt (half).
// Blocks [16384, 20480): eigens -> W0*, W2*, W1* with inverse-DFT scales
// folded in (W0,W2 x0.25, W1 x0.5 — exact powers of two, applied pre-round).
__global__ void prep_fused_kernel(const float* __restrict__ x,
                                  const float* __restrict__ eg) {
    int blk = blockIdx.x;
    if (blk < 16384) {
        int t = blk * 256 + threadIdx.x;          // < 4096*1024
        int b = t >> 10, g = t & 1023;
        float4 v = *reinterpret_cast<const float4*>(x + ((size_t)b << 12) + (g << 2));
        float e = v.x + v.z, o = v.y + v.w;
        __half* r = g_Xt + ((size_t)b << 12);
        r[g]        = __float2half_rn(e + o);
        r[1024 + g] = __float2half_rn(e - o);
        r[2048 + g] = __float2half_rn(v.x - v.z);
        r[3072 + g] = __float2half_rn(v.w - v.y);
    } else {
        int t = (blk - 16384) * 256 + threadIdx.x;  // < 1024*1024
        int y = t >> 10, xg = t & 1023;
        float4 v = *reinterpret_cast<const float4*>(eg + ((size_t)t << 2));
        float e = v.x + v.z, o = v.y + v.w;
        __half Er  = __float2half_rn(0.5f * (v.x - v.z));
        __half Ei  = __float2half_rn(0.5f * (v.w - v.y));
        __half nEi = __float2half_rn(0.5f * (v.y - v.w));
        g_W0[t] = __float2half_rn(0.25f * (e + o));
        g_W2[t] = __float2half_rn(0.25f * (e - o));
        size_t r1 = (size_t)y * 2048;
        size_t r2 = (size_t)(1024 + y) * 2048;
        g_W1[r1 + xg]        = Er;
        g_W1[r1 + 1024 + xg] = nEi;
        g_W1[r2 + xg]        = Ei;
        g_W1[r2 + 1024 + xg] = Er;
    }
}

// ------------------------- post kernel ---------------------------------------
// Pure-add inverse combine (scales pre-folded into W):
//   out0 = Y0'+Y2'+Yr'; out1 = Y0'-Y2'-Yi'; out2 = Y0'+Y2'-Yr'; out3 = Y0'-Y2'+Yi'
// 2 y-groups per thread: half2 loads, two contiguous float4 stores (32B).
__global__ void post_kernel(float* __restrict__ out) {
    int t = blockIdx.x * blockDim.x + threadIdx.x;     // < 4096*512
    int b = t >> 9, y2 = (t & 511) << 1;
    const __half* r = g_Yt + ((size_t)b << 12);
    float2 Y0 = __half22float2(*reinterpret_cast<const __half2*>(r + y2));
    float2 Y2 = __half22float2(*reinterpret_cast<const __half2*>(r + 1024 + y2));
    float2 Yr = __half22float2(*reinterpret_cast<const __half2*>(r + 2048 + y2));
    float2 Yi = __half22float2(*reinterpret_cast<const __half2*>(r + 3072 + y2));
    float* dst = out + ((size_t)b << 12) + (y2 << 2);
    float4 o0, o1;
    o0.x = (Y0.x + Y2.x) + Yr.x;
    o0.y = (Y0.x - Y2.x) - Yi.x;
    o0.z = (Y0.x + Y2.x) - Yr.x;
    o0.w = (Y0.x - Y2.x) + Yi.x;
    o1.x = (Y0.y + Y2.y) + Yr.y;
    o1.y = (Y0.y - Y2.y) - Yi.y;
    o1.z = (Y0.y + Y2.y) - Yr.y;
    o1.w = (Y0.y - Y2.y) + Yi.y;
    *reinterpret_cast<float4*>(dst)     = o0;
    *reinterpret_cast<float4*>(dst + 4) = o1;
}

// ------------------------- host side ----------------------------------------
extern "C" void kernel_launch(void* const* d_in, const int* in_sizes, int n_in,
                              void* d_out, int out_size)
{
    const float* x  = (const float*)d_in[0];
    const float* eg = (const float*)d_in[1];
    if (n_in >= 2 && in_sizes[0] < in_sizes[1]) {   // x: 16.8M elems, eigens: 4.2M
        const float* t = x; x = eg; eg = t;
    }

    cudaFuncSetAttribute(gemm_f16_merged,
                         cudaFuncAttributeMaxDynamicSharedMemorySize, SMEM_GEMM);

    prep_fused_kernel<<<20480, 256>>>(x, eg);
    gemm_f16_merged<<<1024, 256, SMEM_GEMM>>>();
    post_kernel<<<(4096 * 512) / 256, 256>>>((float*)d_out);
}

// round 16
// speedup vs baseline: 1.6765x; 1.1248x over previous
#include <cuda_runtime.h>
#include <cuda_fp16.h>
#include <cstdint>

// ============================================================================
// CirculantLinear via length-4 real DFT diagonalization + 3-mult (Karatsuba)
// complex bin. sm_103-safe ISA only (cp.async + ldmatrix + mma.sync).
//
//   x (4096x4096 f32), eigens (1024x1024x4 f32) -> out (4096x4096 f32)
//
//   prep  : x -> Xt = [X0|X2|Xs|Xr|Xi] (half, Xs = Xr+Xi), width 5120
//           eigens -> W[5] (1024x1024 each):
//             W0 = 0.25(e+o), W1 = 0.25(e-o),
//             W2 = 0.5 Er, W3 = 0.5(Ei-Er), W4 = 0.5(Ei+Er)
//           (inverse-DFT scales folded in; all scales exact powers of two)
//   GEMM  : 5 uniform products Yt[:, gi*1024 : (gi+1)*1024] = Xt_gi @ W[gi]^T
//           (1280 tiles of 128x128, nk2=16, one launch, f32 accum, f16 Yt
//            via smem-staged epilogue)
//   post  : s=Y0+Y2, d=Y0-Y2, pr=k1-k3, pi=k1+k2
//           out = [s+pr, d-pi, s-pr, d+pi]
//
// R16: Karatsuba cuts GEMM MACs 25.8G -> 21.5G (-16.7%); mainloop untouched
//      from the verified R9/R14/R15 kernel.
// ============================================================================

// ------------------------- device scratch (static) --------------------------
__device__ __half g_Xt[(size_t)4096 * 5120];   // 40 MB
__device__ __half g_W [(size_t)5 * 1024 * 1024]; // 10 MB
__device__ __half g_Yt[(size_t)4096 * 5120];   // 40 MB

static constexpr int LDX = 5120;               // Xt / Yt row stride (halfs)
static constexpr int WSZ = 1024 * 1024;

// ------------------------- PTX helpers --------------------------------------
__device__ __forceinline__ uint32_t smem_u32(const void* p) {
    uint32_t a;
    asm("{ .reg .u64 t; cvta.to.shared.u64 t, %1; cvt.u32.u64 %0, t; }"
        : "=r"(a) : "l"(p));
    return a;
}

__device__ __forceinline__ void cp_async16(uint32_t dst, const void* src) {
    asm volatile("cp.async.cg.shared.global [%0], [%1], 16;"
                 :: "r"(dst), "l"(src) : "memory");
}
#define CP_COMMIT() asm volatile("cp.async.commit_group;" ::: "memory")
#define CP_WAIT(N)  asm volatile("cp.async.wait_group %0;" :: "n"(N) : "memory")

__device__ __forceinline__ void ldsm_x4(uint32_t r[4], uint32_t addr) {
    asm volatile("ldmatrix.sync.aligned.m8n8.x4.shared.b16 {%0,%1,%2,%3}, [%4];"
                 : "=r"(r[0]), "=r"(r[1]), "=r"(r[2]), "=r"(r[3]) : "r"(addr));
}

__device__ __forceinline__ void mma16816(float c[4], const uint32_t a[4],
                                         const uint32_t b[2]) {
    asm volatile(
        "mma.sync.aligned.m16n8k16.row.col.f32.f16.f16.f32 "
        "{%0,%1,%2,%3}, {%4,%5,%6,%7}, {%8,%9}, {%0,%1,%2,%3};"
        : "+f"(c[0]), "+f"(c[1]), "+f"(c[2]), "+f"(c[3])
        : "r"(a[0]), "r"(a[1]), "r"(a[2]), "r"(a[3]), "r"(b[0]), "r"(b[1]));
}

// ------------------------- merged GEMM kernel --------------------------------
// CTA tile 128x128, BK=64 halfs per stage, 3-stage cp.async pipeline,
// 2 CTAs/SM. 8 warps as 4(M) x 2(N): warp tile 32x64.
// smem rows exactly 128 B; XOR swizzle chunk' = chunk ^ (row & 7) keeps
// ldmatrix conflict-free.  Mainloop identical to R9/R14/R15.
static constexpr int BK = 64, STAGES = 3;
static constexpr int AB_BYTES  = 128 * 128;             // 16384 per operand
static constexpr int STG_BYTES = 2 * AB_BYTES;          // 32768 per stage
static constexpr int SMEM_GEMM = STAGES * STG_BYTES;    // 98304
static constexpr int NK2 = 16;                          // uniform K = 1024

// Epilogue staging: 128 rows x 272B (256B payload + 16B pad), conflict-free
// both for half2 STS and uint4 LDS (verified in R15).
static constexpr int EPI_ROW_B = 272;

// Tile table: 1280 tiles = 5 gemms x 256 tiles (32 M x 8 N).
__global__ void __launch_bounds__(256, 2) gemm_f16_merged()
{
    extern __shared__ __align__(128) char smem[];
    const uint32_t sb = smem_u32(smem);
    const int tid  = threadIdx.x;
    const int wid  = tid >> 5;
    const int lane = tid & 31;

    // ---- tile decode (uniform) ----
    const int t  = blockIdx.x;
    const int gi = t >> 8;                 // 0..4
    const int u  = t & 255;
    const int m0 = (u >> 3) * 128;
    const int n0 = (u & 7) * 128;

    const __half* Abase = g_Xt + (size_t)m0 * LDX + gi * 1024;
    const __half* Bbase = g_W + (size_t)gi * WSZ + (size_t)n0 * 1024;
    __half*       C     = g_Yt + gi * 1024;

    const int wm = wid & 3;          // M offset wm*32
    const int wn = wid >> 2;         // N offset wn*64

    // --- stage loader: 1024 x 16B chunks each for A and B, 4 per thread ---
    auto load_stage = [&](int s, int kt2) {
        const uint32_t st = sb + s * STG_BYTES;
        const __half* Ag = Abase + kt2 * BK;
        const __half* Bg = Bbase + kt2 * BK;
        #pragma unroll
        for (int i = 0; i < 4; i++) {
            int seg = i * 256 + tid;          // 0..1023
            int row = seg >> 3, c = seg & 7;  // row 0..127, 16B chunk 0..7
            uint32_t so = row * 128 + ((c ^ (row & 7)) << 4);
            cp_async16(st + so,            Ag + (size_t)row * LDX  + c * 8);
            cp_async16(st + AB_BYTES + so, Bg + (size_t)row * 1024 + c * 8);
        }
    };

    float acc[2][8][4];
    #pragma unroll
    for (int mt = 0; mt < 2; mt++)
        #pragma unroll
        for (int nt = 0; nt < 8; nt++)
            #pragma unroll
            for (int i = 0; i < 4; i++) acc[mt][nt][i] = 0.0f;

    // ldmatrix lane addressing (rows + 16B-chunk index within 128B row)
    const int a_row = wm * 32 + (lane & 15);                      // + mt*16
    const int a_cb  = lane >> 4;                                  // chunk bit
    const int arx   = a_row & 7;                                  // swizzle key
    const int b_row = wn * 64 + (lane & 7) + ((lane >> 1) & 8);   // + np*16
    const int b_cb  = (lane >> 3) & 1;
    const int brx   = b_row & 7;

    // --- prologue: stages 0,1 ---
    load_stage(0, 0); CP_COMMIT();
    load_stage(1, 1); CP_COMMIT();

    // --- mainloop: ONE barrier per iteration (slot math as in R8/R9) ---
    int slot = 0;
    for (int kt = 0; kt < NK2; kt++) {
        CP_WAIT(1);
        __syncthreads();

        int kn = kt + 2;
        if (kn < NK2) {
            int ls = slot + 2; if (ls >= 3) ls -= 3;
            load_stage(ls, kn);
        }
        CP_COMMIT();   // commit (possibly empty) keeps group accounting fixed

        const uint32_t As = sb + slot * STG_BYTES;
        const uint32_t Bs = As + AB_BYTES;

        #pragma unroll
        for (int ks = 0; ks < 4; ks++) {      // 4 x (K=16) subchunks
            uint32_t afr[2][4];
            #pragma unroll
            for (int mt = 0; mt < 2; mt++)
                ldsm_x4(afr[mt],
                        As + (a_row + mt * 16) * 128 +
                        (((2 * ks + a_cb) ^ arx) << 4));
            uint32_t bfr[8][2];
            #pragma unroll
            for (int np = 0; np < 4; np++) {
                uint32_t r[4];
                ldsm_x4(r, Bs + (b_row + np * 16) * 128 +
                           (((2 * ks + b_cb) ^ brx) << 4));
                bfr[np * 2 + 0][0] = r[0]; bfr[np * 2 + 0][1] = r[1];
                bfr[np * 2 + 1][0] = r[2]; bfr[np * 2 + 1][1] = r[3];
            }
            #pragma unroll
            for (int mt = 0; mt < 2; mt++)
                #pragma unroll
                for (int nt = 0; nt < 8; nt++)
                    mma16816(acc[mt][nt], afr[mt], bfr[nt]);
        }

        if (++slot == 3) slot = 0;
    }

    // --- epilogue: smem-staged f16 stores to Yt (verified in R15) ---
    CP_WAIT(0);
    __syncthreads();

    {
        const int g = lane >> 2, t4 = lane & 3;
        #pragma unroll
        for (int mt = 0; mt < 2; mt++) {
            int row0 = wm * 32 + mt * 16 + g;
            #pragma unroll
            for (int nt = 0; nt < 8; nt++) {
                int colb = (wn * 64 + nt * 8 + 2 * t4) * 2;   // byte offset
                __half2 h0 = __floats2half2_rn(acc[mt][nt][0], acc[mt][nt][1]);
                __half2 h1 = __floats2half2_rn(acc[mt][nt][2], acc[mt][nt][3]);
                *reinterpret_cast<__half2*>(smem + row0 * EPI_ROW_B + colb)       = h0;
                *reinterpret_cast<__half2*>(smem + (row0 + 8) * EPI_ROW_B + colb) = h1;
            }
        }
    }
    __syncthreads();

    #pragma unroll
    for (int i = 0; i < 8; i++) {
        int idx = i * 256 + tid;              // 0..2047
        int row = idx >> 4, c = idx & 15;
        uint4 v = *reinterpret_cast<const uint4*>(smem + row * EPI_ROW_B + c * 16);
        *reinterpret_cast<uint4*>(C + (size_t)(m0 + row) * LDX + n0 + c * 8) = v;
    }
}

// ------------------------- fused prep kernel ---------------------------------
// Blocks [0, 16384): forward rDFT-4 of x -> Xt = [X0|X2|Xs|Xr|Xi] (half).
// Blocks [16384, 20480): eigens -> W[5] with folded scales.
__global__ void prep_fused_kernel(const float* __restrict__ x,
                                  const float* __restrict__ eg) {
    int blk = blockIdx.x;
    if (blk < 16384) {
        int t = blk * 256 + threadIdx.x;          // < 4096*1024
        int b = t >> 10, g = t & 1023;
        float4 v = *reinterpret_cast<const float4*>(x + ((size_t)b << 12) + (g << 2));
        float e  = v.x + v.z, o = v.y + v.w;
        float Xr = v.x - v.z, Xi = v.w - v.y;
        __half* r = g_Xt + (size_t)b * LDX;
        r[g]        = __float2half_rn(e + o);       // X0
        r[1024 + g] = __float2half_rn(e - o);       // X2
        r[2048 + g] = __float2half_rn(Xr + Xi);     // Xs
        r[3072 + g] = __float2half_rn(Xr);          // Xr
        r[4096 + g] = __float2half_rn(Xi);          // Xi
    } else {
        int t = (blk - 16384) * 256 + threadIdx.x;  // < 1024*1024
        float4 v = *reinterpret_cast<const float4*>(eg + ((size_t)t << 2));
        float e  = v.x + v.z, o = v.y + v.w;
        float Er = v.x - v.z, Ei = v.w - v.y;
        g_W[t]            = __float2half_rn(0.25f * (e + o));    // W0
        g_W[WSZ + t]      = __float2half_rn(0.25f * (e - o));    // W2
        g_W[2 * WSZ + t]  = __float2half_rn(0.5f * Er);          // k1 weight
        g_W[3 * WSZ + t]  = __float2half_rn(0.5f * (Ei - Er));   // k2 weight
        g_W[4 * WSZ + t]  = __float2half_rn(0.5f * (Ei + Er));   // k3 weight
    }
}

// ------------------------- post kernel ---------------------------------------
// s=Y0+Y2, d=Y0-Y2, pr=k1-k3, pi=k1+k2 ; out = [s+pr, d-pi, s-pr, d+pi]
// 2 y-groups per thread: half2 loads, two contiguous float4 stores (32B).
__global__ void post_kernel(float* __restrict__ out) {
    int t = blockIdx.x * blockDim.x + threadIdx.x;     // < 4096*512
    int b = t >> 9, y2 = (t & 511) << 1;
    const __half* r = g_Yt + (size_t)b * LDX;
    float2 Y0 = __half22float2(*reinterpret_cast<const __half2*>(r + y2));
    float2 Y2 = __half22float2(*reinterpret_cast<const __half2*>(r + 1024 + y2));
    float2 k1 = __half22float2(*reinterpret_cast<const __half2*>(r + 2048 + y2));
    float2 k2 = __half22float2(*reinterpret_cast<const __half2*>(r + 3072 + y2));
    float2 k3 = __half22float2(*reinterpret_cast<const __half2*>(r + 4096 + y2));
    float* dst = out + ((size_t)b << 12) + (y2 << 2);
    float4 o0, o1;
    {
        float s = Y0.x + Y2.x, d = Y0.x - Y2.x;
        float pr = k1.x - k3.x, pi = k1.x + k2.x;
        o0.x = s + pr; o0.y = d - pi; o0.z = s - pr; o0.w = d + pi;
    }
    {
        float s = Y0.y + Y2.y, d = Y0.y - Y2.y;
        float pr = k1.y - k3.y, pi = k1.y + k2.y;
        o1.x = s + pr; o1.y = d - pi; o1.z = s - pr; o1.w = d + pi;
    }
    *reinterpret_cast<float4*>(dst)     = o0;
    *reinterpret_cast<float4*>(dst + 4) = o1;
}

// ------------------------- host side ----------------------------------------
extern "C" void kernel_launch(void* const* d_in, const int* in_sizes, int n_in,
                              void* d_out, int out_size)
{
    const float* x  = (const float*)d_in[0];
    const float* eg = (const float*)d_in[1];
    if (n_in >= 2 && in_sizes[0] < in_sizes[1]) {   // x: 16.8M elems, eigens: 4.2M
        const float* t = x; x = eg; eg = t;
    }

    cudaFuncSetAttribute(gemm_f16_merged,
                         cudaFuncAttributeMaxDynamicSharedMemorySize, SMEM_GEMM);

    prep_fused_kernel<<<20480, 256>>>(x, eg);
    gemm_f16_merged<<<1280, 256, SMEM_GEMM>>>();
    post_kernel<<<(4096 * 512) / 256, 256>>>((float*)d_out);
}